// round 16
// baseline (speedup 1.0000x reference)
#include <cuda_runtime.h>
#include <cuda_fp16.h>
#include <stdint.h>
#include <math.h>

#define Mrows   8192
#define Emb     768
#define Nseq    4096
#define Hh      8
#define Dh      96
#define NBH     16

// ---------------- device scratch (fp16 splits) ------------------------------
__device__ __align__(16) __half g_xh[Mrows * Emb];
__device__ __align__(16) __half g_xl[Mrows * Emb];
__device__ __align__(16) __half g_wh[4][Emb * Emb];   // W^T hi [n][k]
__device__ __align__(16) __half g_wl[4][Emb * Emb];
__device__ __align__(16) __half g_qh[NBH * Nseq * Dh];
__device__ __align__(16) __half g_ql[NBH * Nseq * Dh];
__device__ __align__(16) __half g_kh[NBH * Nseq * Dh];
__device__ __align__(16) __half g_kl[NBH * Nseq * Dh];
__device__ __align__(16) __half g_vh[NBH * Dh * Nseq];  // single fp16, [bh][d][n]
__device__ __align__(16) __half g_ao[Mrows * Emb];      // attn out, single fp16

// ---------------- helpers ---------------------------------------------------
__device__ __forceinline__ void mma_f16(float* c, const uint32_t* a,
                                        uint32_t b0, uint32_t b1)
{
    asm volatile(
        "mma.sync.aligned.m16n8k16.row.col.f32.f16.f16.f32 "
        "{%0,%1,%2,%3}, {%4,%5,%6,%7}, {%8,%9}, {%0,%1,%2,%3};\n"
        : "+f"(c[0]), "+f"(c[1]), "+f"(c[2]), "+f"(c[3])
        : "r"(a[0]), "r"(a[1]), "r"(a[2]), "r"(a[3]), "r"(b0), "r"(b1));
}

__device__ __forceinline__ void ldsm4(uint32_t* r, const void* p)
{
    uint32_t a = (uint32_t)__cvta_generic_to_shared(p);
    asm volatile("ldmatrix.sync.aligned.m8n8.x4.shared.b16 {%0,%1,%2,%3}, [%4];\n"
                 : "=r"(r[0]), "=r"(r[1]), "=r"(r[2]), "=r"(r[3]) : "r"(a));
}

__device__ __forceinline__ uint32_t pk(float lo, float hi)
{
    uint32_t r;
    asm("cvt.rn.f16x2.f32 %0, %1, %2;" : "=r"(r) : "f"(hi), "f"(lo));
    return r;
}
__device__ __forceinline__ float rb(float x)
{
    return __half2float(__float2half_rn(x));
}
__device__ __forceinline__ void splitstore(__half* H, __half* L,
                                           size_t idx, float v)
{
    __half h = __float2half_rn(v);
    H[idx] = h;
    L[idx] = __float2half_rn(v - __half2float(h));
}
__device__ __forceinline__ void cpa16(void* dst, const void* src)
{
    uint32_t d = (uint32_t)__cvta_generic_to_shared(dst);
    asm volatile("cp.async.cg.shared.global [%0], [%1], 16;\n" :: "r"(d), "l"(src));
}
#define CPA_COMMIT asm volatile("cp.async.commit_group;\n" ::: "memory")
#define CPA_WAIT0  asm volatile("cp.async.wait_group 0;\n" ::: "memory")
#define CPA_WAIT2  asm volatile("cp.async.wait_group 2;\n" ::: "memory")

// ---------------- conversion kernels ---------------------------------------
__global__ void conv_split_kernel(const float4* __restrict__ X,
                                  uint2* __restrict__ H, uint2* __restrict__ L,
                                  int n4)
{
    int i = blockIdx.x * 256 + threadIdx.x;
    if (i < n4) {
        float4 v = X[i];
        float h0 = rb(v.x), h1 = rb(v.y), h2 = rb(v.z), h3 = rb(v.w);
        uint2 hh, ll;
        hh.x = pk(h0, h1); hh.y = pk(h2, h3);
        ll.x = pk(v.x - h0, v.y - h1);
        ll.y = pk(v.z - h2, v.w - h3);
        H[i] = hh;
        L[i] = ll;
    }
}

__global__ void conv_w_kernel(const float* __restrict__ W0,
                              const float* __restrict__ W1,
                              const float* __restrict__ W2,
                              const float* __restrict__ W3,
                              __half* __restrict__ H,
                              __half* __restrict__ L)
{
    __shared__ float t[32][33];
    int z = blockIdx.z;
    const float* W = (z == 0) ? W0 : (z == 1) ? W1 : (z == 2) ? W2 : W3;
    __half* Hd = H + (size_t)z * Emb * Emb;
    __half* Ld = L + (size_t)z * Emb * Emb;

    int n0 = blockIdx.x * 32, k0 = blockIdx.y * 32;
    int tx = threadIdx.x, ty = threadIdx.y;
#pragma unroll
    for (int i = 0; i < 4; i++)
        t[ty + 8 * i][tx] = W[(size_t)(k0 + ty + 8 * i) * Emb + n0 + tx];
    __syncthreads();
#pragma unroll
    for (int i = 0; i < 4; i++) {
        int n = n0 + ty + 8 * i, k = k0 + tx;
        float v = t[tx][ty + 8 * i];
        __half h = __float2half_rn(v);
        Hd[(size_t)n * Emb + k] = h;
        Ld[(size_t)n * Emb + k] = __float2half_rn(v - __half2float(h));
    }
}

// ---------------- templated split-fp16 GEMM (R14 proven) --------------------
#define GSTR 24
#define G_STG 24576
#define G_AH  0
#define G_AL  6144
#define G_BH  12288
#define G_BL  18432
#define GEMM_SMEM (4 * G_STG)   // 98304

template <int TA, int TB, int MODE>
__global__ __launch_bounds__(256, 2) void gemm_tpl_kernel(
    const __half* __restrict__ Ah, const __half* __restrict__ Al,
    const __half* __restrict__ Wh, const __half* __restrict__ Wl,
    const float* __restrict__ b0v, const float* __restrict__ b1v,
    float* __restrict__ Cf,
    __half* __restrict__ C0h, __half* __restrict__ C0l,
    __half* __restrict__ C1h, __half* __restrict__ C1l)
{
    extern __shared__ char gsm[];
    const int tid = threadIdx.x;
    const int warp = tid >> 5, lane = tid & 31;
    const int g = lane >> 2, t = lane & 3;
    const int lrow = lane & 7, lsel = lane >> 3;
    const int wm = warp & 3, wn = warp >> 2;
    const int row0 = blockIdx.y * 128, col0 = blockIdx.x * 128;

    const __half* Bh;
    const __half* Bl = nullptr;
    const float* bias;
    __half *Ch = nullptr, *Cl = nullptr;
    if (MODE == 1) {
        int z = blockIdx.z;
        Bh = Wh + (size_t)z * Emb * Emb;
        Bl = Wl + (size_t)z * Emb * Emb;
        bias = z ? b1v : b0v;
        Ch = z ? C1h : C0h;
        Cl = z ? C1l : C0l;
    } else {
        Bh = Wh;
        Bl = Wl;
        bias = b0v;
        Ch = C0h;
    }

    float acc[2][8][4];
#pragma unroll
    for (int i = 0; i < 2; i++)
#pragma unroll
        for (int j = 0; j < 8; j++)
#pragma unroll
            for (int c = 0; c < 4; c++) acc[i][j][c] = 0.f;

    auto issue = [&](int k0, int st) {
        char* base = gsm + st * G_STG;
        int r = tid >> 1, c = tid & 1;
        cpa16(base + G_AH + (r * GSTR + c * 8) * 2,
              Ah + (size_t)(row0 + r) * Emb + k0 + c * 8);
        if (TA)
            cpa16(base + G_AL + (r * GSTR + c * 8) * 2,
                  Al + (size_t)(row0 + r) * Emb + k0 + c * 8);
        cpa16(base + G_BH + (r * GSTR + c * 8) * 2,
              Bh + (size_t)(col0 + r) * Emb + k0 + c * 8);
        if (TB)
            cpa16(base + G_BL + (r * GSTR + c * 8) * 2,
                  Bl + (size_t)(col0 + r) * Emb + k0 + c * 8);
    };

    issue(0, 0);  CPA_COMMIT;
    issue(16, 1); CPA_COMMIT;
    issue(32, 2); CPA_COMMIT;

    const int aRow = (lsel & 1) ? 8 : 0;
    const int aCol = (lsel >> 1) ? 8 : 0;
    const int bRow = (lsel >> 1) ? 8 : 0;
    const int bCol = (lsel & 1) ? 8 : 0;

    for (int kk = 0; kk < 48; kk++) {
        CPA_WAIT2;
        __syncthreads();
        if (kk + 3 < 48) issue((kk + 3) * 16, (kk + 3) & 3);
        CPA_COMMIT;

        char* base = gsm + (kk & 3) * G_STG;
        const __half* pAh = (const __half*)(base + G_AH);
        const __half* pAl = (const __half*)(base + G_AL);
        const __half* pBh = (const __half*)(base + G_BH);
        const __half* pBl = (const __half*)(base + G_BL);

        uint32_t ah[2][4], al2[2][4];
#pragma unroll
        for (int mb = 0; mb < 2; mb++) {
            int rr = wm * 32 + mb * 16 + aRow + lrow;
            ldsm4(ah[mb], pAh + rr * GSTR + aCol);
            if (TA) ldsm4(al2[mb], pAl + rr * GSTR + aCol);
        }
#pragma unroll
        for (int p = 0; p < 4; p++) {
            int cn = wn * 64 + p * 16 + bRow + lrow;
            uint32_t bhv[4], blv[4];
            ldsm4(bhv, pBh + cn * GSTR + bCol);
            if (TB) ldsm4(blv, pBl + cn * GSTR + bCol);
#pragma unroll
            for (int mb = 0; mb < 2; mb++) {
                mma_f16(acc[mb][2 * p], ah[mb], bhv[0], bhv[1]);
                mma_f16(acc[mb][2 * p + 1], ah[mb], bhv[2], bhv[3]);
                if (TB) {
                    mma_f16(acc[mb][2 * p], ah[mb], blv[0], blv[1]);
                    mma_f16(acc[mb][2 * p + 1], ah[mb], blv[2], blv[3]);
                }
                if (TA) {
                    mma_f16(acc[mb][2 * p], al2[mb], bhv[0], bhv[1]);
                    mma_f16(acc[mb][2 * p + 1], al2[mb], bhv[2], bhv[3]);
                }
            }
        }
    }

#pragma unroll
    for (int mb = 0; mb < 2; mb++) {
#pragma unroll
        for (int nb = 0; nb < 8; nb++) {
            int r = row0 + wm * 32 + mb * 16 + g;
            int cb = col0 + wn * 64 + nb * 8 + 2 * t;
#pragma unroll
            for (int c = 0; c < 4; c++) {
                int rr = r + (c >= 2 ? 8 : 0);
                int cc = cb + (c & 1);
                float v = acc[mb][nb][c] + bias[cc];
                if (MODE == 0) {
                    Cf[(size_t)rr * Emb + cc] = v;
                } else {
                    int b = rr >> 12, n = rr & 4095;
                    int h = cc / Dh, d = cc - h * Dh;
                    if (MODE == 1) {
                        size_t idx = ((size_t)(b * Hh + h) * Nseq + n) * Dh + d;
                        splitstore(Ch, Cl, idx, v);
                    } else {
                        size_t idx = ((size_t)(b * Hh + h) * Dh + d) * Nseq + n;
                        Ch[idx] = __float2half_rn(v);
                    }
                }
            }
        }
    }
}

// ---------------- flash attention: 128q x 64k, 8 warps ----------------------
// R16: S-phase MMA order term-major (reuse distance 2) — numerics unchanged.
#define QS 120
#define VS 88
#define OFF_QH 0
#define OFF_QL 30720
#define STAGE0 61440
#define STAGE_SZ 47616
#define S_KH 0
#define S_KL 15360
#define S_VH 30720
#define ATTN_SMEM (STAGE0 + 2 * STAGE_SZ)   // 156672

__global__ __launch_bounds__(256) void attn_mma_kernel(
    const __half* __restrict__ Qh, const __half* __restrict__ Ql,
    const __half* __restrict__ Kh, const __half* __restrict__ Kl,
    const __half* __restrict__ Vh,
    __half* __restrict__ Oo)
{
    extern __shared__ char sm[];
    const int tid = threadIdx.x;
    const int warp = tid >> 5, lane = tid & 31;
    const int g = lane >> 2, t = lane & 3;
    const int lrow = lane & 7, lsel = lane >> 3;
    const int bh = blockIdx.y;
    const int q0 = blockIdx.x * 128;

    {
        const char* gQh = (const char*)(Qh + ((size_t)bh * Nseq + q0) * Dh);
        const char* gQl = (const char*)(Ql + ((size_t)bh * Nseq + q0) * Dh);
#pragma unroll
        for (int j = 0; j < 6; j++) {
            int idx = tid + j * 256;
            int r = idx / 12, c = idx - r * 12;
            cpa16(sm + OFF_QH + r * 240 + c * 16, gQh + (size_t)r * 192 + c * 16);
            cpa16(sm + OFF_QL + r * 240 + c * 16, gQl + (size_t)r * 192 + c * 16);
        }
    }

    auto issue = [&](int kt, int st) {
        char* base = sm + STAGE0 + st * STAGE_SZ;
        const char* gKh = (const char*)(Kh + ((size_t)bh * Nseq + kt * 64) * Dh);
        const char* gKl = (const char*)(Kl + ((size_t)bh * Nseq + kt * 64) * Dh);
        const char* gVh = (const char*)(Vh + (size_t)bh * Dh * Nseq + kt * 64);
#pragma unroll
        for (int j = 0; j < 3; j++) {
            int idx = tid + j * 256;
            int r = idx / 12, c = idx - r * 12;
            cpa16(base + S_KH + r * 240 + c * 16, gKh + (size_t)r * 192 + c * 16);
            cpa16(base + S_KL + r * 240 + c * 16, gKl + (size_t)r * 192 + c * 16);
            int rv = idx >> 3, cv = idx & 7;
            cpa16(base + S_VH + rv * 176 + cv * 16, gVh + (size_t)rv * 8192 + cv * 16);
        }
    };

    issue(0, 0);
    CPA_COMMIT;
    CPA_WAIT0;
    __syncthreads();

    const int aRow = (lsel & 1) ? 8 : 0;
    const int aCol = (lsel >> 1) ? 8 : 0;
    const int bRow = (lsel >> 1) ? 8 : 0;
    const int bCol = (lsel & 1) ? 8 : 0;

    uint32_t qh[6][4], ql[6][4];
    {
        const __half* sQh = (const __half*)(sm + OFF_QH);
        const __half* sQl = (const __half*)(sm + OFF_QL);
        int r0 = warp * 16 + aRow + lrow;
#pragma unroll
        for (int kb = 0; kb < 6; kb++) {
            ldsm4(qh[kb], sQh + r0 * QS + kb * 16 + aCol);
            ldsm4(ql[kb], sQl + r0 * QS + kb * 16 + aCol);
        }
    }

    float o[12][4];
#pragma unroll
    for (int i = 0; i < 12; i++)
#pragma unroll
        for (int c = 0; c < 4; c++) o[i][c] = 0.f;
    float m0 = -1e30f, m1 = -1e30f, l0 = 0.f, l1 = 0.f;

    for (int kt = 0; kt < 64; kt++) {
        int cur = kt & 1;
        if (kt > 0) { CPA_WAIT0; }
        __syncthreads();
        if (kt + 1 < 64) { issue(kt + 1, 1 - cur); CPA_COMMIT; }

        const char* base = sm + STAGE0 + cur * STAGE_SZ;
        const __half* sKh = (const __half*)(base + S_KH);
        const __half* sKl = (const __half*)(base + S_KL);
        const __half* sVh = (const __half*)(base + S_VH);

        // --- S = Q K^T (3-term split), term-major MMA order
        float s[8][4];
#pragma unroll
        for (int nb = 0; nb < 8; nb++)
#pragma unroll
            for (int c = 0; c < 4; c++) s[nb][c] = 0.f;

#pragma unroll
        for (int kb = 0; kb < 6; kb++) {
#pragma unroll
            for (int p = 0; p < 4; p++) {
                int rn = p * 16 + bRow + lrow;
                uint32_t bhv[4], blv[4];
                ldsm4(bhv, sKh + rn * QS + kb * 16 + bCol);
                ldsm4(blv, sKl + rn * QS + kb * 16 + bCol);
                // term-major: alternate the two accumulators between terms
                mma_f16(s[2 * p], qh[kb], bhv[0], bhv[1]);
                mma_f16(s[2 * p + 1], qh[kb], bhv[2], bhv[3]);
                mma_f16(s[2 * p], qh[kb], blv[0], blv[1]);
                mma_f16(s[2 * p + 1], qh[kb], blv[2], blv[3]);
                mma_f16(s[2 * p], ql[kb], bhv[0], bhv[1]);
                mma_f16(s[2 * p + 1], ql[kb], bhv[2], bhv[3]);
            }
        }

        // --- online softmax bookkeeping
        float mx0 = -1e30f, mx1 = -1e30f;
#pragma unroll
        for (int nb = 0; nb < 8; nb++) {
            mx0 = fmaxf(mx0, fmaxf(s[nb][0], s[nb][1]));
            mx1 = fmaxf(mx1, fmaxf(s[nb][2], s[nb][3]));
        }
        mx0 = fmaxf(mx0, __shfl_xor_sync(0xffffffffu, mx0, 1));
        mx0 = fmaxf(mx0, __shfl_xor_sync(0xffffffffu, mx0, 2));
        mx1 = fmaxf(mx1, __shfl_xor_sync(0xffffffffu, mx1, 1));
        mx1 = fmaxf(mx1, __shfl_xor_sync(0xffffffffu, mx1, 2));

        float nm0 = fmaxf(m0, mx0), nm1 = fmaxf(m1, mx1);
        float sc0 = __expf(m0 - nm0), sc1 = __expf(m1 - nm1);
        m0 = nm0;
        m1 = nm1;
#pragma unroll
        for (int nbd = 0; nbd < 12; nbd++) {
            o[nbd][0] *= sc0;
            o[nbd][1] *= sc0;
            o[nbd][2] *= sc1;
            o[nbd][3] *= sc1;
        }

        // --- exp -> single fp16 P -> PV (fp32 acc)
        float rs0 = 0.f, rs1 = 0.f;
#pragma unroll
        for (int kb = 0; kb < 4; kb++) {
            float a0 = __expf(s[2 * kb][0] - nm0);
            float a1 = __expf(s[2 * kb][1] - nm0);
            float a2 = __expf(s[2 * kb][2] - nm1);
            float a3 = __expf(s[2 * kb][3] - nm1);
            float b0 = __expf(s[2 * kb + 1][0] - nm0);
            float b1 = __expf(s[2 * kb + 1][1] - nm0);
            float b2 = __expf(s[2 * kb + 1][2] - nm1);
            float b3 = __expf(s[2 * kb + 1][3] - nm1);
            rs0 += a0 + a1 + b0 + b1;
            rs1 += a2 + a3 + b2 + b3;
            uint32_t PH[4];
            PH[0] = pk(a0, a1); PH[1] = pk(a2, a3);
            PH[2] = pk(b0, b1); PH[3] = pk(b2, b3);
#pragma unroll
            for (int p = 0; p < 6; p++) {
                int rn = p * 16 + bRow + lrow;
                uint32_t vhv[4];
                ldsm4(vhv, sVh + rn * VS + kb * 16 + bCol);
                mma_f16(o[2 * p], PH, vhv[0], vhv[1]);
                mma_f16(o[2 * p + 1], PH, vhv[2], vhv[3]);
            }
        }

        rs0 += __shfl_xor_sync(0xffffffffu, rs0, 1);
        rs0 += __shfl_xor_sync(0xffffffffu, rs0, 2);
        rs1 += __shfl_xor_sync(0xffffffffu, rs1, 1);
        rs1 += __shfl_xor_sync(0xffffffffu, rs1, 2);
        l0 = l0 * sc0 + rs0;
        l1 = l1 * sc1 + rs1;
    }

    // --- epilogue: single fp16 output [B,N,E]
    const float isq = 0.1020620726159657f;   // 1/sqrt(96)
    float iv0 = isq / l0, iv1 = isq / l1;
    int b = bh >> 3, h = bh & 7;
    int r0 = q0 + warp * 16 + g;
    size_t row0 = (size_t)b * Nseq + r0;
    size_t row1 = row0 + 8;
#pragma unroll
    for (int nbd = 0; nbd < 12; nbd++) {
        int e = h * Dh + nbd * 8 + 2 * t;
        Oo[row0 * Emb + e]     = __float2half_rn(o[nbd][0] * iv0);
        Oo[row0 * Emb + e + 1] = __float2half_rn(o[nbd][1] * iv0);
        Oo[row1 * Emb + e]     = __float2half_rn(o[nbd][2] * iv1);
        Oo[row1 * Emb + e + 1] = __float2half_rn(o[nbd][3] * iv1);
    }
}

// ---------------------------------------------------------------------------
extern "C" void kernel_launch(void* const* d_in, const int* in_sizes, int n_in,
                              void* d_out, int out_size)
{
    const float* x  = (const float*)d_in[0];
    const float* Wq = (const float*)d_in[1];
    const float* bq = (const float*)d_in[2];
    const float* Wk = (const float*)d_in[3];
    const float* bk = (const float*)d_in[4];
    const float* Wv = (const float*)d_in[5];
    const float* bv = (const float*)d_in[6];
    const float* Wo = (const float*)d_in[7];
    const float* bo = (const float*)d_in[8];
    float* out = (float*)d_out;

    __half *xh, *xl, *wh, *wl, *qh, *ql, *kh, *kl, *vh, *ao;
    cudaGetSymbolAddress((void**)&xh, g_xh);
    cudaGetSymbolAddress((void**)&xl, g_xl);
    cudaGetSymbolAddress((void**)&wh, g_wh);
    cudaGetSymbolAddress((void**)&wl, g_wl);
    cudaGetSymbolAddress((void**)&qh, g_qh);
    cudaGetSymbolAddress((void**)&ql, g_ql);
    cudaGetSymbolAddress((void**)&kh, g_kh);
    cudaGetSymbolAddress((void**)&kl, g_kl);
    cudaGetSymbolAddress((void**)&vh, g_vh);
    cudaGetSymbolAddress((void**)&ao, g_ao);

    cudaFuncSetAttribute(attn_mma_kernel,
                         cudaFuncAttributeMaxDynamicSharedMemorySize, ATTN_SMEM);
    cudaFuncSetAttribute(gemm_tpl_kernel<1, 1, 1>,
                         cudaFuncAttributeMaxDynamicSharedMemorySize, GEMM_SMEM);
    cudaFuncSetAttribute(gemm_tpl_kernel<0, 0, 2>,
                         cudaFuncAttributeMaxDynamicSharedMemorySize, GEMM_SMEM);
    cudaFuncSetAttribute(gemm_tpl_kernel<0, 1, 0>,
                         cudaFuncAttributeMaxDynamicSharedMemorySize, GEMM_SMEM);

    conv_split_kernel<<<(Mrows * Emb / 4 + 255) / 256, 256>>>(
        (const float4*)x, (uint2*)xh, (uint2*)xl, Mrows * Emb / 4);
    dim3 wg(Emb / 32, Emb / 32, 4);
    conv_w_kernel<<<wg, dim3(32, 8)>>>(Wq, Wk, Wv, Wo, wh, wl);

    // Q/K projection (3-term, split store), fused over z in {0,1}
    dim3 gqk(Emb / 128, Mrows / 128, 2);   // (6, 64, 2)
    gemm_tpl_kernel<1, 1, 1><<<gqk, 256, GEMM_SMEM>>>(
        xh, xl, wh, wl, bq, bk, nullptr, qh, ql, kh, kl);

    // V projection (1-term, single fp16 transposed store)
    dim3 gv(Emb / 128, Mrows / 128, 1);
    gemm_tpl_kernel<0, 0, 2><<<gv, 256, GEMM_SMEM>>>(
        xh, nullptr, wh + 2 * (size_t)Emb * Emb, nullptr, bv, nullptr,
        nullptr, vh, nullptr, nullptr, nullptr);

    dim3 ag(Nseq / 128, NBH);              // (32, 16)
    attn_mma_kernel<<<ag, 256, ATTN_SMEM>>>(qh, ql, kh, kl, vh, ao);

    // O projection (2-term: Ah*Wh + Ah*Wl, fp32 out)
    dim3 go(Emb / 128, Mrows / 128, 1);
    gemm_tpl_kernel<0, 1, 0><<<go, 256, GEMM_SMEM>>>(
        ao, nullptr, wh + 3 * (size_t)Emb * Emb, wl + 3 * (size_t)Emb * Emb,
        bo, nullptr, out, nullptr, nullptr, nullptr, nullptr);
}

// round 17
// speedup vs baseline: 1.0319x; 1.0319x over previous
#include <cuda_runtime.h>
#include <cuda_fp16.h>
#include <stdint.h>
#include <math.h>

#define Mrows   8192
#define Emb     768
#define Nseq    4096
#define Hh      8
#define Dh      96
#define NBH     16

// ---------------- device scratch (fp16 splits) ------------------------------
__device__ __align__(16) __half g_xh[Mrows * Emb];
__device__ __align__(16) __half g_xl[Mrows * Emb];
__device__ __align__(16) __half g_wh[4][Emb * Emb];   // W^T hi [n][k]
__device__ __align__(16) __half g_wl[4][Emb * Emb];
__device__ __align__(16) __half g_qh[NBH * Nseq * Dh];
__device__ __align__(16) __half g_ql[NBH * Nseq * Dh];
__device__ __align__(16) __half g_kh[NBH * Nseq * Dh];
__device__ __align__(16) __half g_kl[NBH * Nseq * Dh];
__device__ __align__(16) __half g_vh[NBH * Dh * Nseq];  // single fp16, [bh][d][n]
__device__ __align__(16) __half g_ao[Mrows * Emb];      // attn out, single fp16

// ---------------- helpers ---------------------------------------------------
__device__ __forceinline__ void mma_f16(float* c, const uint32_t* a,
                                        uint32_t b0, uint32_t b1)
{
    asm volatile(
        "mma.sync.aligned.m16n8k16.row.col.f32.f16.f16.f32 "
        "{%0,%1,%2,%3}, {%4,%5,%6,%7}, {%8,%9}, {%0,%1,%2,%3};\n"
        : "+f"(c[0]), "+f"(c[1]), "+f"(c[2]), "+f"(c[3])
        : "r"(a[0]), "r"(a[1]), "r"(a[2]), "r"(a[3]), "r"(b0), "r"(b1));
}

__device__ __forceinline__ void ldsm4(uint32_t* r, const void* p)
{
    uint32_t a = (uint32_t)__cvta_generic_to_shared(p);
    asm volatile("ldmatrix.sync.aligned.m8n8.x4.shared.b16 {%0,%1,%2,%3}, [%4];\n"
                 : "=r"(r[0]), "=r"(r[1]), "=r"(r[2]), "=r"(r[3]) : "r"(a));
}

__device__ __forceinline__ uint32_t pk(float lo, float hi)
{
    uint32_t r;
    asm("cvt.rn.f16x2.f32 %0, %1, %2;" : "=r"(r) : "f"(hi), "f"(lo));
    return r;
}
__device__ __forceinline__ float rb(float x)
{
    return __half2float(__float2half_rn(x));
}
__device__ __forceinline__ void splitstore(__half* H, __half* L,
                                           size_t idx, float v)
{
    __half h = __float2half_rn(v);
    H[idx] = h;
    L[idx] = __float2half_rn(v - __half2float(h));
}
__device__ __forceinline__ void cpa16(void* dst, const void* src)
{
    uint32_t d = (uint32_t)__cvta_generic_to_shared(dst);
    asm volatile("cp.async.cg.shared.global [%0], [%1], 16;\n" :: "r"(d), "l"(src));
}
#define CPA_COMMIT asm volatile("cp.async.commit_group;\n" ::: "memory")
#define CPA_WAIT0  asm volatile("cp.async.wait_group 0;\n" ::: "memory")
#define CPA_WAIT2  asm volatile("cp.async.wait_group 2;\n" ::: "memory")

// ---------------- conversion kernels ---------------------------------------
__global__ void conv_split_kernel(const float4* __restrict__ X,
                                  uint2* __restrict__ H, uint2* __restrict__ L,
                                  int n4)
{
    int i = blockIdx.x * 256 + threadIdx.x;
    if (i < n4) {
        float4 v = X[i];
        float h0 = rb(v.x), h1 = rb(v.y), h2 = rb(v.z), h3 = rb(v.w);
        uint2 hh, ll;
        hh.x = pk(h0, h1); hh.y = pk(h2, h3);
        ll.x = pk(v.x - h0, v.y - h1);
        ll.y = pk(v.z - h2, v.w - h3);
        H[i] = hh;
        L[i] = ll;
    }
}

__global__ void conv_w_kernel(const float* __restrict__ W0,
                              const float* __restrict__ W1,
                              const float* __restrict__ W2,
                              const float* __restrict__ W3,
                              __half* __restrict__ H,
                              __half* __restrict__ L)
{
    __shared__ float t[32][33];
    int z = blockIdx.z;
    const float* W = (z == 0) ? W0 : (z == 1) ? W1 : (z == 2) ? W2 : W3;
    __half* Hd = H + (size_t)z * Emb * Emb;
    __half* Ld = L + (size_t)z * Emb * Emb;

    int n0 = blockIdx.x * 32, k0 = blockIdx.y * 32;
    int tx = threadIdx.x, ty = threadIdx.y;
#pragma unroll
    for (int i = 0; i < 4; i++)
        t[ty + 8 * i][tx] = W[(size_t)(k0 + ty + 8 * i) * Emb + n0 + tx];
    __syncthreads();
#pragma unroll
    for (int i = 0; i < 4; i++) {
        int n = n0 + ty + 8 * i, k = k0 + tx;
        float v = t[tx][ty + 8 * i];
        __half h = __float2half_rn(v);
        Hd[(size_t)n * Emb + k] = h;
        Ld[(size_t)n * Emb + k] = __float2half_rn(v - __half2float(h));
    }
}

// ---------------- templated split-fp16 GEMM body (R14 proven) ---------------
#define GSTR 24
#define G_STG 24576
#define G_AH  0
#define G_AL  6144
#define G_BH  12288
#define G_BL  18432
#define GEMM_SMEM (4 * G_STG)   // 98304

template <int TA, int TB, int MODE>
__device__ __forceinline__ void gemm_body(
    char* gsm,
    const __half* __restrict__ Ah, const __half* __restrict__ Al,
    const __half* __restrict__ Bh, const __half* __restrict__ Bl,
    const float* __restrict__ bias,
    float* __restrict__ Cf,
    __half* __restrict__ Ch, __half* __restrict__ Cl)
{
    const int tid = threadIdx.x;
    const int warp = tid >> 5, lane = tid & 31;
    const int g = lane >> 2, t = lane & 3;
    const int lrow = lane & 7, lsel = lane >> 3;
    const int wm = warp & 3, wn = warp >> 2;
    const int row0 = blockIdx.y * 128, col0 = blockIdx.x * 128;

    float acc[2][8][4];
#pragma unroll
    for (int i = 0; i < 2; i++)
#pragma unroll
        for (int j = 0; j < 8; j++)
#pragma unroll
            for (int c = 0; c < 4; c++) acc[i][j][c] = 0.f;

    auto issue = [&](int k0, int st) {
        char* base = gsm + st * G_STG;
        int r = tid >> 1, c = tid & 1;
        cpa16(base + G_AH + (r * GSTR + c * 8) * 2,
              Ah + (size_t)(row0 + r) * Emb + k0 + c * 8);
        if (TA)
            cpa16(base + G_AL + (r * GSTR + c * 8) * 2,
                  Al + (size_t)(row0 + r) * Emb + k0 + c * 8);
        cpa16(base + G_BH + (r * GSTR + c * 8) * 2,
              Bh + (size_t)(col0 + r) * Emb + k0 + c * 8);
        if (TB)
            cpa16(base + G_BL + (r * GSTR + c * 8) * 2,
                  Bl + (size_t)(col0 + r) * Emb + k0 + c * 8);
    };

    issue(0, 0);  CPA_COMMIT;
    issue(16, 1); CPA_COMMIT;
    issue(32, 2); CPA_COMMIT;

    const int aRow = (lsel & 1) ? 8 : 0;
    const int aCol = (lsel >> 1) ? 8 : 0;
    const int bRow = (lsel >> 1) ? 8 : 0;
    const int bCol = (lsel & 1) ? 8 : 0;

    for (int kk = 0; kk < 48; kk++) {
        CPA_WAIT2;
        __syncthreads();
        if (kk + 3 < 48) issue((kk + 3) * 16, (kk + 3) & 3);
        CPA_COMMIT;

        char* base = gsm + (kk & 3) * G_STG;
        const __half* pAh = (const __half*)(base + G_AH);
        const __half* pAl = (const __half*)(base + G_AL);
        const __half* pBh = (const __half*)(base + G_BH);
        const __half* pBl = (const __half*)(base + G_BL);

        uint32_t ah[2][4], al2[2][4];
#pragma unroll
        for (int mb = 0; mb < 2; mb++) {
            int rr = wm * 32 + mb * 16 + aRow + lrow;
            ldsm4(ah[mb], pAh + rr * GSTR + aCol);
            if (TA) ldsm4(al2[mb], pAl + rr * GSTR + aCol);
        }
#pragma unroll
        for (int p = 0; p < 4; p++) {
            int cn = wn * 64 + p * 16 + bRow + lrow;
            uint32_t bhv[4], blv[4];
            ldsm4(bhv, pBh + cn * GSTR + bCol);
            if (TB) ldsm4(blv, pBl + cn * GSTR + bCol);
#pragma unroll
            for (int mb = 0; mb < 2; mb++) {
                mma_f16(acc[mb][2 * p], ah[mb], bhv[0], bhv[1]);
                mma_f16(acc[mb][2 * p + 1], ah[mb], bhv[2], bhv[3]);
                if (TB) {
                    mma_f16(acc[mb][2 * p], ah[mb], blv[0], blv[1]);
                    mma_f16(acc[mb][2 * p + 1], ah[mb], blv[2], blv[3]);
                }
                if (TA) {
                    mma_f16(acc[mb][2 * p], al2[mb], bhv[0], bhv[1]);
                    mma_f16(acc[mb][2 * p + 1], al2[mb], bhv[2], bhv[3]);
                }
            }
        }
    }

#pragma unroll
    for (int mb = 0; mb < 2; mb++) {
#pragma unroll
        for (int nb = 0; nb < 8; nb++) {
            int r = row0 + wm * 32 + mb * 16 + g;
            int cb = col0 + wn * 64 + nb * 8 + 2 * t;
#pragma unroll
            for (int c = 0; c < 4; c++) {
                int rr = r + (c >= 2 ? 8 : 0);
                int cc = cb + (c & 1);
                float v = acc[mb][nb][c] + bias[cc];
                if (MODE == 0) {
                    Cf[(size_t)rr * Emb + cc] = v;
                } else {
                    int b = rr >> 12, n = rr & 4095;
                    int h = cc / Dh, d = cc - h * Dh;
                    if (MODE == 1) {
                        size_t idx = ((size_t)(b * Hh + h) * Nseq + n) * Dh + d;
                        splitstore(Ch, Cl, idx, v);
                    } else {
                        size_t idx = ((size_t)(b * Hh + h) * Dh + d) * Nseq + n;
                        Ch[idx] = __float2half_rn(v);
                    }
                }
            }
        }
    }
}

// Fused QKV: z in {0,1} -> Q/K (3-term split store); z==2 -> V (1-term, fp16 T)
__global__ __launch_bounds__(256, 2) void gemm_qkv_kernel(
    const __half* __restrict__ xh, const __half* __restrict__ xl,
    const __half* __restrict__ wh, const __half* __restrict__ wl,
    const float* __restrict__ bq, const float* __restrict__ bk,
    const float* __restrict__ bv,
    __half* __restrict__ qh, __half* __restrict__ ql,
    __half* __restrict__ kh, __half* __restrict__ kl,
    __half* __restrict__ vh)
{
    extern __shared__ char gsm[];
    int z = blockIdx.z;
    if (z == 2) {
        gemm_body<0, 0, 2>(gsm, xh, nullptr,
                           wh + 2 * (size_t)Emb * Emb, nullptr,
                           bv, nullptr, vh, nullptr);
    } else {
        gemm_body<1, 1, 1>(gsm, xh, xl,
                           wh + (size_t)z * Emb * Emb, wl + (size_t)z * Emb * Emb,
                           z ? bk : bq, nullptr,
                           z ? kh : qh, z ? kl : ql);
    }
}

// O projection (2-term, fp32 out)
__global__ __launch_bounds__(256, 2) void gemm_o_kernel(
    const __half* __restrict__ ao,
    const __half* __restrict__ wh, const __half* __restrict__ wl,
    const float* __restrict__ bo, float* __restrict__ out)
{
    extern __shared__ char gsm[];
    gemm_body<0, 1, 0>(gsm, ao, nullptr, wh, wl, bo, out, nullptr, nullptr);
}

// ---------------- flash attention: 128q x 64k, 8 warps (R14 proven) ---------
#define QS 120
#define VS 88
#define OFF_QH 0
#define OFF_QL 30720
#define STAGE0 61440
#define STAGE_SZ 47616
#define S_KH 0
#define S_KL 15360
#define S_VH 30720
#define ATTN_SMEM (STAGE0 + 2 * STAGE_SZ)   // 156672

__global__ __launch_bounds__(256) void attn_mma_kernel(
    const __half* __restrict__ Qh, const __half* __restrict__ Ql,
    const __half* __restrict__ Kh, const __half* __restrict__ Kl,
    const __half* __restrict__ Vh,
    __half* __restrict__ Oo)
{
    extern __shared__ char sm[];
    const int tid = threadIdx.x;
    const int warp = tid >> 5, lane = tid & 31;
    const int g = lane >> 2, t = lane & 3;
    const int lrow = lane & 7, lsel = lane >> 3;
    const int bh = blockIdx.y;
    const int q0 = blockIdx.x * 128;

    {
        const char* gQh = (const char*)(Qh + ((size_t)bh * Nseq + q0) * Dh);
        const char* gQl = (const char*)(Ql + ((size_t)bh * Nseq + q0) * Dh);
#pragma unroll
        for (int j = 0; j < 6; j++) {
            int idx = tid + j * 256;
            int r = idx / 12, c = idx - r * 12;
            cpa16(sm + OFF_QH + r * 240 + c * 16, gQh + (size_t)r * 192 + c * 16);
            cpa16(sm + OFF_QL + r * 240 + c * 16, gQl + (size_t)r * 192 + c * 16);
        }
    }

    auto issue = [&](int kt, int st) {
        char* base = sm + STAGE0 + st * STAGE_SZ;
        const char* gKh = (const char*)(Kh + ((size_t)bh * Nseq + kt * 64) * Dh);
        const char* gKl = (const char*)(Kl + ((size_t)bh * Nseq + kt * 64) * Dh);
        const char* gVh = (const char*)(Vh + (size_t)bh * Dh * Nseq + kt * 64);
#pragma unroll
        for (int j = 0; j < 3; j++) {
            int idx = tid + j * 256;
            int r = idx / 12, c = idx - r * 12;
            cpa16(base + S_KH + r * 240 + c * 16, gKh + (size_t)r * 192 + c * 16);
            cpa16(base + S_KL + r * 240 + c * 16, gKl + (size_t)r * 192 + c * 16);
            int rv = idx >> 3, cv = idx & 7;
            cpa16(base + S_VH + rv * 176 + cv * 16, gVh + (size_t)rv * 8192 + cv * 16);
        }
    };

    issue(0, 0);
    CPA_COMMIT;
    CPA_WAIT0;
    __syncthreads();

    const int aRow = (lsel & 1) ? 8 : 0;
    const int aCol = (lsel >> 1) ? 8 : 0;
    const int bRow = (lsel >> 1) ? 8 : 0;
    const int bCol = (lsel & 1) ? 8 : 0;

    uint32_t qh[6][4], ql[6][4];
    {
        const __half* sQh = (const __half*)(sm + OFF_QH);
        const __half* sQl = (const __half*)(sm + OFF_QL);
        int r0 = warp * 16 + aRow + lrow;
#pragma unroll
        for (int kb = 0; kb < 6; kb++) {
            ldsm4(qh[kb], sQh + r0 * QS + kb * 16 + aCol);
            ldsm4(ql[kb], sQl + r0 * QS + kb * 16 + aCol);
        }
    }

    float o[12][4];
#pragma unroll
    for (int i = 0; i < 12; i++)
#pragma unroll
        for (int c = 0; c < 4; c++) o[i][c] = 0.f;
    float m0 = -1e30f, m1 = -1e30f, l0 = 0.f, l1 = 0.f;

    for (int kt = 0; kt < 64; kt++) {
        int cur = kt & 1;
        if (kt > 0) { CPA_WAIT0; }
        __syncthreads();
        if (kt + 1 < 64) { issue(kt + 1, 1 - cur); CPA_COMMIT; }

        const char* base = sm + STAGE0 + cur * STAGE_SZ;
        const __half* sKh = (const __half*)(base + S_KH);
        const __half* sKl = (const __half*)(base + S_KL);
        const __half* sVh = (const __half*)(base + S_VH);

        // --- S = Q K^T (3-term split)
        float s[8][4];
#pragma unroll
        for (int nb = 0; nb < 8; nb++)
#pragma unroll
            for (int c = 0; c < 4; c++) s[nb][c] = 0.f;

#pragma unroll
        for (int kb = 0; kb < 6; kb++) {
#pragma unroll
            for (int p = 0; p < 4; p++) {
                int rn = p * 16 + bRow + lrow;
                uint32_t bhv[4], blv[4];
                ldsm4(bhv, sKh + rn * QS + kb * 16 + bCol);
                ldsm4(blv, sKl + rn * QS + kb * 16 + bCol);
                mma_f16(s[2 * p], qh[kb], bhv[0], bhv[1]);
                mma_f16(s[2 * p], qh[kb], blv[0], blv[1]);
                mma_f16(s[2 * p], ql[kb], bhv[0], bhv[1]);
                mma_f16(s[2 * p + 1], qh[kb], bhv[2], bhv[3]);
                mma_f16(s[2 * p + 1], qh[kb], blv[2], blv[3]);
                mma_f16(s[2 * p + 1], ql[kb], bhv[2], bhv[3]);
            }
        }

        // --- online softmax bookkeeping
        float mx0 = -1e30f, mx1 = -1e30f;
#pragma unroll
        for (int nb = 0; nb < 8; nb++) {
            mx0 = fmaxf(mx0, fmaxf(s[nb][0], s[nb][1]));
            mx1 = fmaxf(mx1, fmaxf(s[nb][2], s[nb][3]));
        }
        mx0 = fmaxf(mx0, __shfl_xor_sync(0xffffffffu, mx0, 1));
        mx0 = fmaxf(mx0, __shfl_xor_sync(0xffffffffu, mx0, 2));
        mx1 = fmaxf(mx1, __shfl_xor_sync(0xffffffffu, mx1, 1));
        mx1 = fmaxf(mx1, __shfl_xor_sync(0xffffffffu, mx1, 2));

        float nm0 = fmaxf(m0, mx0), nm1 = fmaxf(m1, mx1);
        float sc0 = __expf(m0 - nm0), sc1 = __expf(m1 - nm1);
        m0 = nm0;
        m1 = nm1;
#pragma unroll
        for (int nbd = 0; nbd < 12; nbd++) {
            o[nbd][0] *= sc0;
            o[nbd][1] *= sc0;
            o[nbd][2] *= sc1;
            o[nbd][3] *= sc1;
        }

        // --- exp -> single fp16 P -> PV (fp32 acc)
        float rs0 = 0.f, rs1 = 0.f;
#pragma unroll
        for (int kb = 0; kb < 4; kb++) {
            float a0 = __expf(s[2 * kb][0] - nm0);
            float a1 = __expf(s[2 * kb][1] - nm0);
            float a2 = __expf(s[2 * kb][2] - nm1);
            float a3 = __expf(s[2 * kb][3] - nm1);
            float b0 = __expf(s[2 * kb + 1][0] - nm0);
            float b1 = __expf(s[2 * kb + 1][1] - nm0);
            float b2 = __expf(s[2 * kb + 1][2] - nm1);
            float b3 = __expf(s[2 * kb + 1][3] - nm1);
            rs0 += a0 + a1 + b0 + b1;
            rs1 += a2 + a3 + b2 + b3;
            uint32_t PH[4];
            PH[0] = pk(a0, a1); PH[1] = pk(a2, a3);
            PH[2] = pk(b0, b1); PH[3] = pk(b2, b3);
#pragma unroll
            for (int p = 0; p < 6; p++) {
                int rn = p * 16 + bRow + lrow;
                uint32_t vhv[4];
                ldsm4(vhv, sVh + rn * VS + kb * 16 + bCol);
                mma_f16(o[2 * p], PH, vhv[0], vhv[1]);
                mma_f16(o[2 * p + 1], PH, vhv[2], vhv[3]);
            }
        }

        rs0 += __shfl_xor_sync(0xffffffffu, rs0, 1);
        rs0 += __shfl_xor_sync(0xffffffffu, rs0, 2);
        rs1 += __shfl_xor_sync(0xffffffffu, rs1, 1);
        rs1 += __shfl_xor_sync(0xffffffffu, rs1, 2);
        l0 = l0 * sc0 + rs0;
        l1 = l1 * sc1 + rs1;
    }

    // --- epilogue: single fp16 output [B,N,E]
    const float isq = 0.1020620726159657f;   // 1/sqrt(96)
    float iv0 = isq / l0, iv1 = isq / l1;
    int b = bh >> 3, h = bh & 7;
    int r0 = q0 + warp * 16 + g;
    size_t row0 = (size_t)b * Nseq + r0;
    size_t row1 = row0 + 8;
#pragma unroll
    for (int nbd = 0; nbd < 12; nbd++) {
        int e = h * Dh + nbd * 8 + 2 * t;
        Oo[row0 * Emb + e]     = __float2half_rn(o[nbd][0] * iv0);
        Oo[row0 * Emb + e + 1] = __float2half_rn(o[nbd][1] * iv0);
        Oo[row1 * Emb + e]     = __float2half_rn(o[nbd][2] * iv1);
        Oo[row1 * Emb + e + 1] = __float2half_rn(o[nbd][3] * iv1);
    }
}

// ---------------------------------------------------------------------------
extern "C" void kernel_launch(void* const* d_in, const int* in_sizes, int n_in,
                              void* d_out, int out_size)
{
    const float* x  = (const float*)d_in[0];
    const float* Wq = (const float*)d_in[1];
    const float* bq = (const float*)d_in[2];
    const float* Wk = (const float*)d_in[3];
    const float* bk = (const float*)d_in[4];
    const float* Wv = (const float*)d_in[5];
    const float* bv = (const float*)d_in[6];
    const float* Wo = (const float*)d_in[7];
    const float* bo = (const float*)d_in[8];
    float* out = (float*)d_out;

    __half *xh, *xl, *wh, *wl, *qh, *ql, *kh, *kl, *vh, *ao;
    cudaGetSymbolAddress((void**)&xh, g_xh);
    cudaGetSymbolAddress((void**)&xl, g_xl);
    cudaGetSymbolAddress((void**)&wh, g_wh);
    cudaGetSymbolAddress((void**)&wl, g_wl);
    cudaGetSymbolAddress((void**)&qh, g_qh);
    cudaGetSymbolAddress((void**)&ql, g_ql);
    cudaGetSymbolAddress((void**)&kh, g_kh);
    cudaGetSymbolAddress((void**)&kl, g_kl);
    cudaGetSymbolAddress((void**)&vh, g_vh);
    cudaGetSymbolAddress((void**)&ao, g_ao);

    cudaFuncSetAttribute(attn_mma_kernel,
                         cudaFuncAttributeMaxDynamicSharedMemorySize, ATTN_SMEM);
    cudaFuncSetAttribute(gemm_qkv_kernel,
                         cudaFuncAttributeMaxDynamicSharedMemorySize, GEMM_SMEM);
    cudaFuncSetAttribute(gemm_o_kernel,
                         cudaFuncAttributeMaxDynamicSharedMemorySize, GEMM_SMEM);

    conv_split_kernel<<<(Mrows * Emb / 4 + 255) / 256, 256>>>(
        (const float4*)x, (uint2*)xh, (uint2*)xl, Mrows * Emb / 4);
    dim3 wg(Emb / 32, Emb / 32, 4);
    conv_w_kernel<<<wg, dim3(32, 8)>>>(Wq, Wk, Wv, Wo, wh, wl);

    // fused Q/K/V projection in ONE launch (z: 0=Q, 1=K, 2=V)
    dim3 gqkv(Emb / 128, Mrows / 128, 3);   // (6, 64, 3) = 1152 CTAs
    gemm_qkv_kernel<<<gqkv, 256, GEMM_SMEM>>>(
        xh, xl, wh, wl, bq, bk, bv, qh, ql, kh, kl, vh);

    dim3 ag(Nseq / 128, NBH);               // (32, 16)
    attn_mma_kernel<<<ag, 256, ATTN_SMEM>>>(qh, ql, kh, kl, vh, ao);

    // O projection (2-term: Ah*Wh + Ah*Wl, fp32 out)
    dim3 go(Emb / 128, Mrows / 128, 1);
    gemm_o_kernel<<<go, 256, GEMM_SMEM>>>(
        ao, wh + 3 * (size_t)Emb * Emb, wl + 3 * (size_t)Emb * Emb, bo, out);
}